// round 12
// baseline (speedup 1.0000x reference)
#include <cuda_runtime.h>
#include <cstdint>
#include <cfloat>
#include <math.h>

#define VOCAB      128000
#define NVEC       (VOCAB / 4)      // 32000 float4 per row (NOT divisible by TILE_VEC!)
#define BLOCK      256
#define KEEP       50
#define VPT        2                // float4 vectors per thread per tile
#define TILE_VEC   (BLOCK * VPT)    // 512 vectors = 2048 elements per tile
#define BUF        4096             // candidate buffer entries, ~33KB static smem
#define TRIGGER    (BUF - TILE_VEC * 4) // 2048: compact before next tile could overflow

// PRNG: partitionable threefry (modern JAX default): bits = o0 ^ o1 of x=(0,i).
// CONFIRMED mostly-right by round 11 (80% row match with an unrelated OOB bug).

// ---------------- threefry2x32 (JAX-exact) ----------------
__device__ __forceinline__ uint32_t rotl32(uint32_t v, int d) {
    return (v << d) | (v >> (32 - d));
}

__device__ __forceinline__ void threefry2x32(uint32_t k0, uint32_t k1,
                                             uint32_t x0, uint32_t x1,
                                             uint32_t& o0, uint32_t& o1) {
    const uint32_t ks2 = k0 ^ k1 ^ 0x1BD11BDAu;
    x0 += k0; x1 += k1;
    x0 += x1; x1 = rotl32(x1, 13); x1 ^= x0;
    x0 += x1; x1 = rotl32(x1, 15); x1 ^= x0;
    x0 += x1; x1 = rotl32(x1, 26); x1 ^= x0;
    x0 += x1; x1 = rotl32(x1,  6); x1 ^= x0;
    x0 += k1; x1 += ks2 + 1u;
    x0 += x1; x1 = rotl32(x1, 17); x1 ^= x0;
    x0 += x1; x1 = rotl32(x1, 29); x1 ^= x0;
    x0 += x1; x1 = rotl32(x1, 16); x1 ^= x0;
    x0 += x1; x1 = rotl32(x1, 24); x1 ^= x0;
    x0 += ks2; x1 += k0 + 2u;
    x0 += x1; x1 = rotl32(x1, 13); x1 ^= x0;
    x0 += x1; x1 = rotl32(x1, 15); x1 ^= x0;
    x0 += x1; x1 = rotl32(x1, 26); x1 ^= x0;
    x0 += x1; x1 = rotl32(x1,  6); x1 ^= x0;
    x0 += k0; x1 += k1 + 3u;
    x0 += x1; x1 = rotl32(x1, 17); x1 ^= x0;
    x0 += x1; x1 = rotl32(x1, 29); x1 ^= x0;
    x0 += x1; x1 = rotl32(x1, 16); x1 ^= x0;
    x0 += x1; x1 = rotl32(x1, 24); x1 ^= x0;
    x0 += k1; x1 += ks2 + 4u;
    x0 += x1; x1 = rotl32(x1, 13); x1 ^= x0;
    x0 += x1; x1 = rotl32(x1, 15); x1 ^= x0;
    x0 += x1; x1 = rotl32(x1, 26); x1 ^= x0;
    x0 += x1; x1 = rotl32(x1,  6); x1 ^= x0;
    x0 += ks2; x1 += k0 + 5u;
    o0 = x0; o1 = x1;
}

__device__ __forceinline__ uint32_t jax_random_bits(uint32_t i) {
    uint32_t o0, o1;
    threefry2x32(0u, 42u, 0u, i, o0, o1);
    return o0 ^ o1;
}

// comparator: is (vb, ib) "better" than (va, ia)?  (lax.top_k: value desc, index asc)
__device__ __forceinline__ bool better(float vb, int ib, float va, int ia) {
    return (vb > va) || (vb == va && ib < ia);
}

// Bitonic sort of s_val/s_idx[0..n), best-first. n power of 2, n <= BUF.
__device__ void bitonic_sort(float* s_val, int* s_idx, int n) {
    for (int k = 2; k <= n; k <<= 1) {
        for (int j = k >> 1; j > 0; j >>= 1) {
            for (int i = threadIdx.x; i < n; i += BLOCK) {
                int ixj = i ^ j;
                if (ixj > i) {
                    float v1 = s_val[i], v2 = s_val[ixj];
                    int   a  = s_idx[i], b  = s_idx[ixj];
                    bool best_first = ((i & k) == 0);
                    bool sw = best_first ? better(v2, b, v1, a)
                                         : better(v1, a, v2, b);
                    if (sw) {
                        s_val[i] = v2; s_idx[i] = b;
                        s_val[ixj] = v1; s_idx[ixj] = a;
                    }
                }
            }
            __syncthreads();
        }
    }
}

// Sort buffer contents (count entries, padded to pow2 with -inf sentinels).
__device__ void sort_buffer(float* s_val, int* s_idx, int count) {
    int n = 64;
    while (n < count) n <<= 1;     // n <= BUF since count <= BUF
    for (int i = count + threadIdx.x; i < n; i += BLOCK) {
        s_val[i] = -FLT_MAX;
        s_idx[i] = 0x7FFFFFFF;
    }
    __syncthreads();
    bitonic_sort(s_val, s_idx, n);
}

__global__ __launch_bounds__(BLOCK)
void topk_sample_kernel(const float* __restrict__ logits, float* __restrict__ out,
                        int rows) {
    __shared__ float s_val[BUF];
    __shared__ int   s_idx[BUF];
    __shared__ int   s_count;
    __shared__ float s_thresh;
    __shared__ float s_vg[KEEP];

    const int row = blockIdx.x;
    const int tid = threadIdx.x;
    const float4* rp = (const float4*)(logits + (size_t)row * VOCAB);

    if (tid == 0) { s_count = 0; s_thresh = -FLT_MAX; }
    __syncthreads();

    float thresh = -FLT_MAX;

    // ---------------- single streaming pass with dynamic-threshold filter ----------------
    // NVEC = 32000 is NOT a multiple of TILE_VEC=512 -> bounds guard is REQUIRED.
    for (int base = 0; base < NVEC; base += TILE_VEC) {
        float4 v[VPT];
        bool   ok[VPT];
#pragma unroll
        for (int u = 0; u < VPT; u++) {
            int idx = base + tid + u * BLOCK;
            ok[u] = (idx < NVEC);
            if (ok[u]) v[u] = rp[idx];
        }
#pragma unroll
        for (int u = 0; u < VPT; u++) {
            if (!ok[u]) continue;
            int e = (base + tid + u * BLOCK) * 4;
            float x;
            x = v[u].x; if (x > thresh) { int p = atomicAdd(&s_count, 1); s_val[p] = x; s_idx[p] = e;     }
            x = v[u].y; if (x > thresh) { int p = atomicAdd(&s_count, 1); s_val[p] = x; s_idx[p] = e + 1; }
            x = v[u].z; if (x > thresh) { int p = atomicAdd(&s_count, 1); s_val[p] = x; s_idx[p] = e + 2; }
            x = v[u].w; if (x > thresh) { int p = atomicAdd(&s_count, 1); s_val[p] = x; s_idx[p] = e + 3; }
        }
        __syncthreads();
        int cnt = s_count;   // uniform (no writes since barrier); max 2047+2048 = 4095 < BUF
        if (cnt >= TRIGGER) {
            sort_buffer(s_val, s_idx, cnt);
            if (tid == 0) {
                s_count  = KEEP;
                s_thresh = s_val[KEEP - 1];
            }
            __syncthreads();
        }
        thresh = s_thresh;
    }

    // ---------------- final selection ----------------
    int cnt = s_count;
    sort_buffer(s_val, s_idx, cnt);   // [0..49] = top-k (value desc, index asc)

    // ---------------- gumbel-max sampling (JAX categorical, key(42), partitionable) ----------------
    if (tid < KEEP) {
        uint32_t flat = (uint32_t)(row * KEEP + tid);
        uint32_t bits = jax_random_bits(flat);
        float f = __uint_as_float((bits >> 9) | 0x3F800000u) - 1.0f;
        float u = fmaxf(f, 1.17549435e-38f);   // minval = finfo(f32).tiny
        float g = -logf(-logf(u));             // f32 log chain
        s_vg[tid] = s_val[tid] + g;
    }
    __syncthreads();

    if (tid == 0) {
        int best = 0;
        float bv = s_vg[0];
#pragma unroll
        for (int j = 1; j < KEEP; j++) {
            if (s_vg[j] > bv) { bv = s_vg[j]; best = j; }   // strict > : first wins
        }
        // Output compared as float32 (vocab index < 2^24, exact in f32).
        out[row] = (float)s_idx[best];
    }
}

extern "C" void kernel_launch(void* const* d_in, const int* in_sizes, int n_in,
                              void* d_out, int out_size) {
    const float* logits = (const float*)d_in[0];
    float* out = (float*)d_out;        // __output__ is float32
    int rows = in_sizes[0] / VOCAB;    // 256

    topk_sample_kernel<<<rows, BLOCK>>>(logits, out, rows);
}

// round 13
// speedup vs baseline: 5.9602x; 5.9602x over previous
#include <cuda_runtime.h>
#include <cstdint>
#include <cfloat>
#include <math.h>

#define VOCAB       128000
#define ROWS_MAX    256
#define KEEP        50
#define FILT_THRESH 3.0f          // row 50th-largest ~ z=3.36 for N(0,1); P(row count<50) ~ 7e-21
#define SLICES      16
#define SLICE_ELEMS (VOCAB / SLICES)   // 8000
#define SLICE_VEC   (SLICE_ELEMS / 4)  // 2000 float4
#define CAP         2048               // per-row candidate capacity (mean ~173)
#define BLOCK       256

// -------- global scratch (static __device__: allocation-free) --------
__device__ int   g_cnt [ROWS_MAX];
__device__ float g_cval[ROWS_MAX][CAP];
__device__ int   g_cidx[ROWS_MAX][CAP];

// ---------------- threefry2x32 (JAX-exact, partitionable layout) ----------------
__device__ __forceinline__ uint32_t rotl32(uint32_t v, int d) {
    return (v << d) | (v >> (32 - d));
}

__device__ __forceinline__ void threefry2x32(uint32_t k0, uint32_t k1,
                                             uint32_t x0, uint32_t x1,
                                             uint32_t& o0, uint32_t& o1) {
    const uint32_t ks2 = k0 ^ k1 ^ 0x1BD11BDAu;
    x0 += k0; x1 += k1;
    x0 += x1; x1 = rotl32(x1, 13); x1 ^= x0;
    x0 += x1; x1 = rotl32(x1, 15); x1 ^= x0;
    x0 += x1; x1 = rotl32(x1, 26); x1 ^= x0;
    x0 += x1; x1 = rotl32(x1,  6); x1 ^= x0;
    x0 += k1; x1 += ks2 + 1u;
    x0 += x1; x1 = rotl32(x1, 17); x1 ^= x0;
    x0 += x1; x1 = rotl32(x1, 29); x1 ^= x0;
    x0 += x1; x1 = rotl32(x1, 16); x1 ^= x0;
    x0 += x1; x1 = rotl32(x1, 24); x1 ^= x0;
    x0 += ks2; x1 += k0 + 2u;
    x0 += x1; x1 = rotl32(x1, 13); x1 ^= x0;
    x0 += x1; x1 = rotl32(x1, 15); x1 ^= x0;
    x0 += x1; x1 = rotl32(x1, 26); x1 ^= x0;
    x0 += x1; x1 = rotl32(x1,  6); x1 ^= x0;
    x0 += k0; x1 += k1 + 3u;
    x0 += x1; x1 = rotl32(x1, 17); x1 ^= x0;
    x0 += x1; x1 = rotl32(x1, 29); x1 ^= x0;
    x0 += x1; x1 = rotl32(x1, 16); x1 ^= x0;
    x0 += x1; x1 = rotl32(x1, 24); x1 ^= x0;
    x0 += k1; x1 += ks2 + 4u;
    x0 += x1; x1 = rotl32(x1, 13); x1 ^= x0;
    x0 += x1; x1 = rotl32(x1, 15); x1 ^= x0;
    x0 += x1; x1 = rotl32(x1, 26); x1 ^= x0;
    x0 += x1; x1 = rotl32(x1,  6); x1 ^= x0;
    x0 += ks2; x1 += k0 + 5u;
    o0 = x0; o1 = x1;
}

__device__ __forceinline__ uint32_t jax_random_bits(uint32_t i) {
    uint32_t o0, o1;
    threefry2x32(0u, 42u, 0u, i, o0, o1);
    return o0 ^ o1;
}

// comparator: (value desc, index asc) — lax.top_k order
__device__ __forceinline__ bool better(float vb, int ib, float va, int ia) {
    return (vb > va) || (vb == va && ib < ia);
}

// Bitonic sort of s_val/s_idx[0..n), best-first. n power of 2, n <= CAP.
__device__ void bitonic_sort(float* s_val, int* s_idx, int n) {
    for (int k = 2; k <= n; k <<= 1) {
        for (int j = k >> 1; j > 0; j >>= 1) {
            for (int i = threadIdx.x; i < n; i += BLOCK) {
                int ixj = i ^ j;
                if (ixj > i) {
                    float v1 = s_val[i], v2 = s_val[ixj];
                    int   a  = s_idx[i], b  = s_idx[ixj];
                    bool best_first = ((i & k) == 0);
                    bool sw = best_first ? better(v2, b, v1, a)
                                         : better(v1, a, v2, b);
                    if (sw) {
                        s_val[i] = v2; s_idx[i] = b;
                        s_val[ixj] = v1; s_idx[ixj] = a;
                    }
                }
            }
            __syncthreads();
        }
    }
}

// Pad to pow2 with -inf sentinels, then sort.
__device__ void sort_buffer(float* s_val, int* s_idx, int count) {
    int n = 64;
    while (n < count) n <<= 1;      // n <= CAP
    for (int i = count + threadIdx.x; i < n; i += BLOCK) {
        s_val[i] = -FLT_MAX;
        s_idx[i] = 0x7FFFFFFF;
    }
    __syncthreads();
    bitonic_sort(s_val, s_idx, n);
}

// ================= K0: zero per-row counters =================
__global__ void zero_counters(int rows) {
    int i = threadIdx.x;
    if (i < rows) g_cnt[i] = 0;
}

// ================= K1: streaming threshold filter =================
__global__ __launch_bounds__(BLOCK)
void filter_kernel(const float* __restrict__ logits) {
    const int b   = blockIdx.x;
    const int row = b >> 4;                 // / SLICES
    const int sl  = b & (SLICES - 1);
    const float4* rp = (const float4*)(logits + (size_t)row * VOCAB) + sl * SLICE_VEC;
    const int ebase = sl * SLICE_ELEMS;

#pragma unroll 4
    for (int v = threadIdx.x; v < SLICE_VEC; v += BLOCK) {
        float4 f = rp[v];
        int e = ebase + v * 4;
        if (f.x > FILT_THRESH) { int p = atomicAdd(&g_cnt[row], 1); if (p < CAP) { g_cval[row][p] = f.x; g_cidx[row][p] = e;     } }
        if (f.y > FILT_THRESH) { int p = atomicAdd(&g_cnt[row], 1); if (p < CAP) { g_cval[row][p] = f.y; g_cidx[row][p] = e + 1; } }
        if (f.z > FILT_THRESH) { int p = atomicAdd(&g_cnt[row], 1); if (p < CAP) { g_cval[row][p] = f.z; g_cidx[row][p] = e + 2; } }
        if (f.w > FILT_THRESH) { int p = atomicAdd(&g_cnt[row], 1); if (p < CAP) { g_cval[row][p] = f.w; g_cidx[row][p] = e + 3; } }
    }
}

// --------- exact fallback: full-row scan (never triggers on bench data) ---------
__device__ int fallback_collect(const float* __restrict__ logits, int row,
                                float* s_val, int* s_idx) {
    __shared__ int   s_count;
    __shared__ float s_thresh;
    const int tid = threadIdx.x;
    const float4* rp = (const float4*)(logits + (size_t)row * VOCAB);
    const int nvec = VOCAB / 4;        // 32000

    if (tid == 0) { s_count = 0; s_thresh = -FLT_MAX; }
    __syncthreads();
    float thresh = -FLT_MAX;

    for (int base = 0; base < nvec; base += BLOCK) {   // tiles of 1024 elems
        int idx = base + tid;
        if (idx < nvec) {
            float4 f = rp[idx];
            int e = idx * 4;
            if (f.x > thresh) { int p = atomicAdd(&s_count, 1); if (p < CAP) { s_val[p] = f.x; s_idx[p] = e;     } }
            if (f.y > thresh) { int p = atomicAdd(&s_count, 1); if (p < CAP) { s_val[p] = f.y; s_idx[p] = e + 1; } }
            if (f.z > thresh) { int p = atomicAdd(&s_count, 1); if (p < CAP) { s_val[p] = f.z; s_idx[p] = e + 2; } }
            if (f.w > thresh) { int p = atomicAdd(&s_count, 1); if (p < CAP) { s_val[p] = f.w; s_idx[p] = e + 3; } }
        }
        __syncthreads();
        int cnt = s_count;
        if (cnt > CAP) cnt = CAP;
        if (cnt >= CAP - BLOCK * 4) {     // compact before possible overflow
            sort_buffer(s_val, s_idx, cnt);
            if (tid == 0) { s_count = KEEP; s_thresh = s_val[KEEP - 1]; }
            __syncthreads();
        }
        thresh = s_thresh;
    }
    int cnt = s_count;
    return cnt > CAP ? CAP : cnt;
}

// ================= K2: merge + sort + gumbel sample =================
__global__ __launch_bounds__(BLOCK)
void sample_kernel(const float* __restrict__ logits, float* __restrict__ out,
                   int rows) {
    __shared__ float s_val[CAP];
    __shared__ int   s_idx[CAP];
    __shared__ float s_vg[KEEP];

    const int row = blockIdx.x;
    const int tid = threadIdx.x;

    int cnt = g_cnt[row];
    if (cnt > CAP) cnt = CAP;          // pathological clamp (never on bench data)

    if (cnt >= KEEP) {
        for (int i = tid; i < cnt; i += BLOCK) {
            s_val[i] = g_cval[row][i];
            s_idx[i] = g_cidx[row][i];
        }
        __syncthreads();
    } else {
        // exact full-row rescan (correctness for arbitrary data; never runs here)
        cnt = fallback_collect(logits, row, s_val, s_idx);
    }

    sort_buffer(s_val, s_idx, cnt);    // [0..KEEP-1] = exact top-k (value desc, idx asc)

    if (tid < KEEP) {
        uint32_t flat = (uint32_t)(row * KEEP + tid);
        uint32_t bits = jax_random_bits(flat);
        float f = __uint_as_float((bits >> 9) | 0x3F800000u) - 1.0f;
        float u = fmaxf(f, 1.17549435e-38f);   // minval = finfo(f32).tiny
        float g = -logf(-logf(u));             // f32 log chain
        s_vg[tid] = s_val[tid] + g;
    }
    __syncthreads();

    if (tid == 0) {
        int best = 0;
        float bv = s_vg[0];
#pragma unroll
        for (int j = 1; j < KEEP; j++) {
            if (s_vg[j] > bv) { bv = s_vg[j]; best = j; }   // strict > : first wins
        }
        out[row] = (float)s_idx[best];     // output compared as float32
    }
}

extern "C" void kernel_launch(void* const* d_in, const int* in_sizes, int n_in,
                              void* d_out, int out_size) {
    const float* logits = (const float*)d_in[0];
    float* out = (float*)d_out;
    int rows = in_sizes[0] / VOCAB;        // 256

    zero_counters<<<1, BLOCK>>>(rows);
    filter_kernel<<<rows * SLICES, BLOCK>>>(logits);
    sample_kernel<<<rows, BLOCK>>>(logits, out, rows);
}

// round 14
// speedup vs baseline: 7.3157x; 1.2274x over previous
#include <cuda_runtime.h>
#include <cstdint>
#include <cfloat>
#include <math.h>

#define VOCAB       128000
#define NVEC        (VOCAB / 4)       // 32000 float4 per row
#define BLOCK       512
#define KEEP        50
#define VPT         4                 // float4 per thread per iteration
#define TILE_VEC    (BLOCK * VPT)     // 2048 vectors = 8192 elements
#define CAP         1024              // candidate buffer (mean occupancy ~173)
#define FILT_THRESH 3.0f              // row 50th-largest ~ z=3.36; P(count<50) ~ 7e-21

// ---------------- threefry2x32 (JAX-exact, partitionable layout) ----------------
__device__ __forceinline__ uint32_t rotl32(uint32_t v, int d) {
    return (v << d) | (v >> (32 - d));
}

__device__ __forceinline__ void threefry2x32(uint32_t k0, uint32_t k1,
                                             uint32_t x0, uint32_t x1,
                                             uint32_t& o0, uint32_t& o1) {
    const uint32_t ks2 = k0 ^ k1 ^ 0x1BD11BDAu;
    x0 += k0; x1 += k1;
    x0 += x1; x1 = rotl32(x1, 13); x1 ^= x0;
    x0 += x1; x1 = rotl32(x1, 15); x1 ^= x0;
    x0 += x1; x1 = rotl32(x1, 26); x1 ^= x0;
    x0 += x1; x1 = rotl32(x1,  6); x1 ^= x0;
    x0 += k1; x1 += ks2 + 1u;
    x0 += x1; x1 = rotl32(x1, 17); x1 ^= x0;
    x0 += x1; x1 = rotl32(x1, 29); x1 ^= x0;
    x0 += x1; x1 = rotl32(x1, 16); x1 ^= x0;
    x0 += x1; x1 = rotl32(x1, 24); x1 ^= x0;
    x0 += ks2; x1 += k0 + 2u;
    x0 += x1; x1 = rotl32(x1, 13); x1 ^= x0;
    x0 += x1; x1 = rotl32(x1, 15); x1 ^= x0;
    x0 += x1; x1 = rotl32(x1, 26); x1 ^= x0;
    x0 += x1; x1 = rotl32(x1,  6); x1 ^= x0;
    x0 += k0; x1 += k1 + 3u;
    x0 += x1; x1 = rotl32(x1, 17); x1 ^= x0;
    x0 += x1; x1 = rotl32(x1, 29); x1 ^= x0;
    x0 += x1; x1 = rotl32(x1, 16); x1 ^= x0;
    x0 += x1; x1 = rotl32(x1, 24); x1 ^= x0;
    x0 += k1; x1 += ks2 + 4u;
    x0 += x1; x1 = rotl32(x1, 13); x1 ^= x0;
    x0 += x1; x1 = rotl32(x1, 15); x1 ^= x0;
    x0 += x1; x1 = rotl32(x1, 26); x1 ^= x0;
    x0 += x1; x1 = rotl32(x1,  6); x1 ^= x0;
    x0 += ks2; x1 += k0 + 5u;
    o0 = x0; o1 = x1;
}

__device__ __forceinline__ uint32_t jax_random_bits(uint32_t i) {
    uint32_t o0, o1;
    threefry2x32(0u, 42u, 0u, i, o0, o1);
    return o0 ^ o1;
}

// comparator: (value desc, index asc) — lax.top_k order
__device__ __forceinline__ bool better(float vb, int ib, float va, int ia) {
    return (vb > va) || (vb == va && ib < ia);
}

// Bitonic sort of s_val/s_idx[0..n), best-first. n power of 2, n <= CAP.
__device__ void bitonic_sort(float* s_val, int* s_idx, int n) {
    for (int k = 2; k <= n; k <<= 1) {
        for (int j = k >> 1; j > 0; j >>= 1) {
            for (int i = threadIdx.x; i < n; i += BLOCK) {
                int ixj = i ^ j;
                if (ixj > i) {
                    float v1 = s_val[i], v2 = s_val[ixj];
                    int   a  = s_idx[i], b  = s_idx[ixj];
                    bool best_first = ((i & k) == 0);
                    bool sw = best_first ? better(v2, b, v1, a)
                                         : better(v1, a, v2, b);
                    if (sw) {
                        s_val[i] = v2; s_idx[i] = b;
                        s_val[ixj] = v1; s_idx[ixj] = a;
                    }
                }
            }
            __syncthreads();
        }
    }
}

// Pad [count..n) with -inf sentinels, then sort.
__device__ void sort_buffer(float* s_val, int* s_idx, int count) {
    int n = 64;
    while (n < count) n <<= 1;      // n <= CAP
    for (int i = count + threadIdx.x; i < n; i += BLOCK) {
        s_val[i] = -FLT_MAX;
        s_idx[i] = 0x7FFFFFFF;
    }
    __syncthreads();
    bitonic_sort(s_val, s_idx, n);
}

// --------- exact fallback: dynamic-threshold full rescan (verified in R12) ---------
// Never triggers on the bench input; guarantees exactness for arbitrary data.
__device__ int fallback_collect(const float4* __restrict__ rp,
                                float* s_val, int* s_idx,
                                int* p_count, float* p_thresh) {
    const int tid = threadIdx.x;
    if (tid == 0) { *p_count = 0; *p_thresh = -FLT_MAX; }
    __syncthreads();
    float thresh = -FLT_MAX;

    for (int base = 0; base < NVEC; base += BLOCK) {
        int idx = base + tid;
        if (idx < NVEC) {
            float4 f = rp[idx];
            int e = idx * 4;
            if (f.x > thresh) { int p = atomicAdd(p_count, 1); if (p < CAP) { s_val[p] = f.x; s_idx[p] = e;     } }
            if (f.y > thresh) { int p = atomicAdd(p_count, 1); if (p < CAP) { s_val[p] = f.y; s_idx[p] = e + 1; } }
            if (f.z > thresh) { int p = atomicAdd(p_count, 1); if (p < CAP) { s_val[p] = f.z; s_idx[p] = e + 2; } }
            if (f.w > thresh) { int p = atomicAdd(p_count, 1); if (p < CAP) { s_val[p] = f.w; s_idx[p] = e + 3; } }
        }
        __syncthreads();
        int cnt = *p_count;
        if (cnt > CAP) cnt = CAP;
        if (cnt >= CAP - BLOCK * 4 / 2) {    // compact well before overflow
            sort_buffer(s_val, s_idx, cnt);
            if (tid == 0) { *p_count = KEEP; *p_thresh = s_val[KEEP - 1]; }
            __syncthreads();
        }
        thresh = *p_thresh;
    }
    int cnt = *p_count;
    return cnt > CAP ? CAP : cnt;
}

// ================= fused: filter + sort + gumbel sample =================
__global__ __launch_bounds__(BLOCK)
void fused_topk_sample(const float* __restrict__ logits, float* __restrict__ out,
                       int rows) {
    __shared__ float s_val[CAP];
    __shared__ int   s_idx[CAP];
    __shared__ int   s_count;
    __shared__ float s_thresh;
    __shared__ float s_vg[KEEP];

    const int row = blockIdx.x;
    const int tid = threadIdx.x;
    const float4* rp = (const float4*)(logits + (size_t)row * VOCAB);

    if (tid == 0) s_count = 0;
    __syncthreads();

    // ---- streaming static-threshold filter: no barriers, deep MLP ----
    for (int base = 0; base < NVEC; base += TILE_VEC) {
        float4 f[VPT];
        bool   ok[VPT];
#pragma unroll
        for (int u = 0; u < VPT; u++) {
            int idx = base + tid + u * BLOCK;
            ok[u] = (idx < NVEC);
            if (ok[u]) f[u] = rp[idx];
        }
#pragma unroll
        for (int u = 0; u < VPT; u++) {
            if (!ok[u]) continue;
            int e = (base + tid + u * BLOCK) * 4;
            if (f[u].x > FILT_THRESH) { int p = atomicAdd(&s_count, 1); if (p < CAP) { s_val[p] = f[u].x; s_idx[p] = e;     } }
            if (f[u].y > FILT_THRESH) { int p = atomicAdd(&s_count, 1); if (p < CAP) { s_val[p] = f[u].y; s_idx[p] = e + 1; } }
            if (f[u].z > FILT_THRESH) { int p = atomicAdd(&s_count, 1); if (p < CAP) { s_val[p] = f[u].z; s_idx[p] = e + 2; } }
            if (f[u].w > FILT_THRESH) { int p = atomicAdd(&s_count, 1); if (p < CAP) { s_val[p] = f[u].w; s_idx[p] = e + 3; } }
        }
    }
    __syncthreads();

    int cnt = s_count;
    if (cnt < KEEP || cnt > CAP) {
        // exact fallback (never on bench data): full dynamic-threshold rescan
        cnt = fallback_collect(rp, s_val, s_idx, &s_count, &s_thresh);
    }

    sort_buffer(s_val, s_idx, cnt);    // [0..KEEP-1] = exact top-k (value desc, idx asc)

    // ---- gumbel-max sampling (JAX categorical, key(42), partitionable threefry) ----
    if (tid < KEEP) {
        uint32_t flat = (uint32_t)(row * KEEP + tid);
        uint32_t bits = jax_random_bits(flat);
        float f = __uint_as_float((bits >> 9) | 0x3F800000u) - 1.0f;
        float u = fmaxf(f, 1.17549435e-38f);   // minval = finfo(f32).tiny
        float g = -logf(-logf(u));             // f32 log chain
        s_vg[tid] = s_val[tid] + g;
    }
    __syncthreads();

    if (tid == 0) {
        int best = 0;
        float bv = s_vg[0];
#pragma unroll
        for (int j = 1; j < KEEP; j++) {
            if (s_vg[j] > bv) { bv = s_vg[j]; best = j; }   // strict > : first wins
        }
        out[row] = (float)s_idx[best];     // output compared as float32
    }
}

extern "C" void kernel_launch(void* const* d_in, const int* in_sizes, int n_in,
                              void* d_out, int out_size) {
    const float* logits = (const float*)d_in[0];
    float* out = (float*)d_out;
    int rows = in_sizes[0] / VOCAB;        // 256

    fused_topk_sample<<<rows, BLOCK>>>(logits, out, rows);
}

// round 15
// speedup vs baseline: 9.6906x; 1.3246x over previous
#include <cuda_runtime.h>
#include <cstdint>
#include <cfloat>
#include <math.h>

#define VOCAB       128000
#define NVEC        (VOCAB / 4)       // 32000 float4 per row
#define BLOCK       1024              // 32 warps/CTA -> 64 warps on 2-CTA SMs (100% occ)
#define KEEP        50
#define VPT         4                 // float4 per thread per iteration
#define TILE_VEC    (BLOCK * VPT)     // 4096 vectors = 16384 elements
#define CAP         1024              // candidate buffer (mean occupancy ~173)
#define FILT_THRESH 3.0f              // row 50th-largest ~ z=3.36; P(count<50) ~ 7e-21

// ---------------- threefry2x32 (JAX-exact, partitionable layout) ----------------
__device__ __forceinline__ uint32_t rotl32(uint32_t v, int d) {
    return (v << d) | (v >> (32 - d));
}

__device__ __forceinline__ void threefry2x32(uint32_t k0, uint32_t k1,
                                             uint32_t x0, uint32_t x1,
                                             uint32_t& o0, uint32_t& o1) {
    const uint32_t ks2 = k0 ^ k1 ^ 0x1BD11BDAu;
    x0 += k0; x1 += k1;
    x0 += x1; x1 = rotl32(x1, 13); x1 ^= x0;
    x0 += x1; x1 = rotl32(x1, 15); x1 ^= x0;
    x0 += x1; x1 = rotl32(x1, 26); x1 ^= x0;
    x0 += x1; x1 = rotl32(x1,  6); x1 ^= x0;
    x0 += k1; x1 += ks2 + 1u;
    x0 += x1; x1 = rotl32(x1, 17); x1 ^= x0;
    x0 += x1; x1 = rotl32(x1, 29); x1 ^= x0;
    x0 += x1; x1 = rotl32(x1, 16); x1 ^= x0;
    x0 += x1; x1 = rotl32(x1, 24); x1 ^= x0;
    x0 += ks2; x1 += k0 + 2u;
    x0 += x1; x1 = rotl32(x1, 13); x1 ^= x0;
    x0 += x1; x1 = rotl32(x1, 15); x1 ^= x0;
    x0 += x1; x1 = rotl32(x1, 26); x1 ^= x0;
    x0 += x1; x1 = rotl32(x1,  6); x1 ^= x0;
    x0 += k0; x1 += k1 + 3u;
    x0 += x1; x1 = rotl32(x1, 17); x1 ^= x0;
    x0 += x1; x1 = rotl32(x1, 29); x1 ^= x0;
    x0 += x1; x1 = rotl32(x1, 16); x1 ^= x0;
    x0 += x1; x1 = rotl32(x1, 24); x1 ^= x0;
    x0 += k1; x1 += ks2 + 4u;
    x0 += x1; x1 = rotl32(x1, 13); x1 ^= x0;
    x0 += x1; x1 = rotl32(x1, 15); x1 ^= x0;
    x0 += x1; x1 = rotl32(x1, 26); x1 ^= x0;
    x0 += x1; x1 = rotl32(x1,  6); x1 ^= x0;
    x0 += ks2; x1 += k0 + 5u;
    o0 = x0; o1 = x1;
}

__device__ __forceinline__ uint32_t jax_random_bits(uint32_t i) {
    uint32_t o0, o1;
    threefry2x32(0u, 42u, 0u, i, o0, o1);
    return o0 ^ o1;
}

// comparator: (value desc, index asc) — lax.top_k order
__device__ __forceinline__ bool better(float vb, int ib, float va, int ia) {
    return (vb > va) || (vb == va && ib < ia);
}

// Bitonic sort of s_val/s_idx[0..n), best-first. n power of 2, n <= CAP.
__device__ void bitonic_sort(float* s_val, int* s_idx, int n) {
    for (int k = 2; k <= n; k <<= 1) {
        for (int j = k >> 1; j > 0; j >>= 1) {
            for (int i = threadIdx.x; i < n; i += BLOCK) {
                int ixj = i ^ j;
                if (ixj > i) {
                    float v1 = s_val[i], v2 = s_val[ixj];
                    int   a  = s_idx[i], b  = s_idx[ixj];
                    bool best_first = ((i & k) == 0);
                    bool sw = best_first ? better(v2, b, v1, a)
                                         : better(v1, a, v2, b);
                    if (sw) {
                        s_val[i] = v2; s_idx[i] = b;
                        s_val[ixj] = v1; s_idx[ixj] = a;
                    }
                }
            }
            __syncthreads();
        }
    }
}

// Pad [count..n) with -inf sentinels, then sort.
__device__ void sort_buffer(float* s_val, int* s_idx, int count) {
    int n = 64;
    while (n < count) n <<= 1;      // n <= CAP
    for (int i = count + threadIdx.x; i < n; i += BLOCK) {
        s_val[i] = -FLT_MAX;
        s_idx[i] = 0x7FFFFFFF;
    }
    __syncthreads();
    bitonic_sort(s_val, s_idx, n);
}

// --------- exact fallback: dynamic-threshold full rescan (verified R12) ---------
// Never triggers on the bench input; guarantees exactness for arbitrary data.
__device__ int fallback_collect(const float4* __restrict__ rp,
                                float* s_val, int* s_idx,
                                int* p_count, float* p_thresh) {
    const int tid = threadIdx.x;
    if (tid == 0) { *p_count = 0; *p_thresh = -FLT_MAX; }
    __syncthreads();
    float thresh = -FLT_MAX;

    for (int base = 0; base < NVEC; base += BLOCK) {
        int idx = base + tid;
        if (idx < NVEC) {
            float4 f = rp[idx];
            int e = idx * 4;
            if (f.x > thresh) { int p = atomicAdd(p_count, 1); if (p < CAP) { s_val[p] = f.x; s_idx[p] = e;     } }
            if (f.y > thresh) { int p = atomicAdd(p_count, 1); if (p < CAP) { s_val[p] = f.y; s_idx[p] = e + 1; } }
            if (f.z > thresh) { int p = atomicAdd(p_count, 1); if (p < CAP) { s_val[p] = f.z; s_idx[p] = e + 2; } }
            if (f.w > thresh) { int p = atomicAdd(p_count, 1); if (p < CAP) { s_val[p] = f.w; s_idx[p] = e + 3; } }
        }
        __syncthreads();
        int cnt = *p_count;
        if (cnt > CAP) cnt = CAP;
        if (cnt >= CAP / 2) {               // compact well before overflow
            sort_buffer(s_val, s_idx, cnt);
            if (tid == 0) { *p_count = KEEP; *p_thresh = s_val[KEEP - 1]; }
            __syncthreads();
        }
        thresh = *p_thresh;
    }
    int cnt = *p_count;
    return cnt > CAP ? CAP : cnt;
}

// ================= fused: filter + sort + gumbel sample =================
__global__ __launch_bounds__(BLOCK, 2)
void fused_topk_sample(const float* __restrict__ logits, float* __restrict__ out,
                       int rows) {
    __shared__ float s_val[CAP];
    __shared__ int   s_idx[CAP];
    __shared__ int   s_count;
    __shared__ float s_thresh;
    __shared__ float s_vg[KEEP];

    const int row = blockIdx.x;
    const int tid = threadIdx.x;
    const float4* rp = (const float4*)(logits + (size_t)row * VOCAB);

    if (tid == 0) s_count = 0;
    __syncthreads();

    // ---- streaming static-threshold filter: no barriers, deep MLP, evict-first ----
    for (int base = 0; base < NVEC; base += TILE_VEC) {
        float4 f[VPT];
        bool   ok[VPT];
#pragma unroll
        for (int u = 0; u < VPT; u++) {
            int idx = base + tid + u * BLOCK;
            ok[u] = (idx < NVEC);
            if (ok[u]) f[u] = __ldcs(&rp[idx]);   // read-once stream: don't pollute L1
        }
#pragma unroll
        for (int u = 0; u < VPT; u++) {
            if (!ok[u]) continue;
            int e = (base + tid + u * BLOCK) * 4;
            if (f[u].x > FILT_THRESH) { int p = atomicAdd(&s_count, 1); if (p < CAP) { s_val[p] = f[u].x; s_idx[p] = e;     } }
            if (f[u].y > FILT_THRESH) { int p = atomicAdd(&s_count, 1); if (p < CAP) { s_val[p] = f[u].y; s_idx[p] = e + 1; } }
            if (f[u].z > FILT_THRESH) { int p = atomicAdd(&s_count, 1); if (p < CAP) { s_val[p] = f[u].z; s_idx[p] = e + 2; } }
            if (f[u].w > FILT_THRESH) { int p = atomicAdd(&s_count, 1); if (p < CAP) { s_val[p] = f[u].w; s_idx[p] = e + 3; } }
        }
    }
    __syncthreads();

    int cnt = s_count;
    if (cnt < KEEP || cnt > CAP) {
        // exact fallback (never on bench data): full dynamic-threshold rescan
        cnt = fallback_collect(rp, s_val, s_idx, &s_count, &s_thresh);
    }

    sort_buffer(s_val, s_idx, cnt);    // [0..KEEP-1] = exact top-k (value desc, idx asc)

    // ---- gumbel-max sampling (JAX categorical, key(42), partitionable threefry) ----
    if (tid < KEEP) {
        uint32_t flat = (uint32_t)(row * KEEP + tid);
        uint32_t bits = jax_random_bits(flat);
        float f = __uint_as_float((bits >> 9) | 0x3F800000u) - 1.0f;
        float u = fmaxf(f, 1.17549435e-38f);   // minval = finfo(f32).tiny
        float g = -logf(-logf(u));             // f32 log chain
        s_vg[tid] = s_val[tid] + g;
    }
    __syncthreads();

    if (tid == 0) {
        int best = 0;
        float bv = s_vg[0];
#pragma unroll
        for (int j = 1; j < KEEP; j++) {
            if (s_vg[j] > bv) { bv = s_vg[j]; best = j; }   // strict > : first wins
        }
        out[row] = (float)s_idx[best];     // output compared as float32
    }
}

extern "C" void kernel_launch(void* const* d_in, const int* in_sizes, int n_in,
                              void* d_out, int out_size) {
    const float* logits = (const float*)d_in[0];
    float* out = (float*)d_out;
    int rows = in_sizes[0] / VOCAB;        // 256

    fused_topk_sample<<<rows, BLOCK>>>(logits, out, rows);
}